// round 12
// baseline (speedup 1.0000x reference)
#include <cuda_runtime.h>

// QLSTM split into two kernels:
//  1) proj_kernel: xproj[t,b,48] = x @ [Wgates_x | Wi2k] + (bias+theta | bi2k)
//     (pure x-dependent work, embarrassingly parallel, DRAM-bound)
//  2) qlstm_rec: 512-step recurrence, one warp per batch element,
//     exchanges via vectorized shared memory (LSU-op minimized).

#define FULLMASK 0xffffffffu

static constexpr int T_STEPS = 512;
static constexpr int BSZ     = 1024;
static constexpr int IN_DIM  = 64;
static constexpr int HID     = 8;
static constexpr int PCOLS   = 48;            // 32 gate cols + 8 ky cols + 8 pad
static constexpr int WARPS_PER_BLOCK = 4;
static constexpr int THREADS = WARPS_PER_BLOCK * 32;
static constexpr int NBLOCKS = BSZ / WARPS_PER_BLOCK;
static constexpr int NROWS   = T_STEPS * BSZ; // 524288

typedef unsigned long long ull;

__device__ float g_xproj[(size_t)NROWS * PCOLS];   // ~100 MB static scratch

__device__ __forceinline__ ull pack2(float lo, float hi) {
    ull r;
    asm("mov.b64 %0, {%1, %2};" : "=l"(r) : "f"(lo), "f"(hi));
    return r;
}
__device__ __forceinline__ void unpack2(ull v, float& lo, float& hi) {
    asm("mov.b64 {%0, %1}, %2;" : "=f"(lo), "=f"(hi) : "l"(v));
}
__device__ __forceinline__ ull ffma2(ull a, ull b, ull c) {
    ull d;
    asm("fma.rn.f32x2 %0, %1, %2, %3;" : "=l"(d) : "l"(a), "l"(b), "l"(c));
    return d;
}

// ---------------------------------------------------------------------------
// Kernel 1: x projections. Block = 128 threads, 512 rows per block in 4
// chunks of 128. Lane = output column (gate g*8+j for cols 0..31; lanes 0..7
// also produce ky cols 32..39). Weights register-resident; x tile staged in
// smem and read via uniform (broadcast) LDS.128.
// ---------------------------------------------------------------------------
__global__ void __launch_bounds__(128)
proj_kernel(const float* __restrict__ x,
            const float* __restrict__ Wf, const float* __restrict__ bf, const float* __restrict__ th_f,
            const float* __restrict__ Wi, const float* __restrict__ bi, const float* __restrict__ th_i,
            const float* __restrict__ Wu, const float* __restrict__ bu, const float* __restrict__ th_u,
            const float* __restrict__ Wo, const float* __restrict__ bo, const float* __restrict__ th_o,
            const float* __restrict__ Wi2k, const float* __restrict__ bi2k)
{
    __shared__ __align__(16) float xs[128 * IN_DIM];
    const int tid  = threadIdx.x;
    const int lane = tid & 31;
    const int w    = tid >> 5;
    const int g    = lane >> 3;
    const int j    = lane & 7;

    const float* WA = (g == 0) ? Wf : (g == 1) ? Wi : (g == 2) ? Wu : Wo;
    const float* bA = (g == 0) ? bf : (g == 1) ? bi : (g == 2) ? bu : bo;
    const float* tA = (g == 0) ? th_f : (g == 1) ? th_i : (g == 2) ? th_u : th_o;

    ull wA2[32], wB2[32];
    #pragma unroll
    for (int m = 0; m < 32; m++)
        wA2[m] = pack2(WA[(2 * m) * HID + j], WA[(2 * m + 1) * HID + j]);
    const float biasA = bA[j] + tA[j];        // bias + RX theta folded

    float biasB = 0.0f;
    if (lane < 8) {
        #pragma unroll
        for (int m = 0; m < 32; m++)
            wB2[m] = pack2(Wi2k[(2 * m) * HID + lane], Wi2k[(2 * m + 1) * HID + lane]);
        biasB = bi2k[lane];
    } else {
        #pragma unroll
        for (int m = 0; m < 32; m++) wB2[m] = 0ull;
    }

    const int row0 = blockIdx.x * 512;
    for (int chunk = 0; chunk < 4; chunk++) {
        const int rbase = row0 + chunk * 128;
        __syncthreads();                       // protect xs reuse
        // stage 128 rows x 64 floats, fully coalesced
        const float4* src = (const float4*)(x + (size_t)rbase * IN_DIM);
        float4* dst = (float4*)xs;
        #pragma unroll
        for (int k2 = 0; k2 < 16; k2++)
            dst[tid + k2 * 128] = src[tid + k2 * 128];
        __syncthreads();

        // warp w computes rows [w*32, w*32+32)
        #pragma unroll 4
        for (int ri = 0; ri < 32; ri++) {
            const int r = w * 32 + ri;
            const float4* xr = (const float4*)(xs + r * IN_DIM);
            ull a2a = 0ull, a2b = 0ull, b2a = 0ull, b2b = 0ull;
            #pragma unroll
            for (int m4 = 0; m4 < 16; m4++) {
                float4 xv = xr[m4];            // uniform address -> broadcast
                ull xlo = pack2(xv.x, xv.y);
                ull xhi = pack2(xv.z, xv.w);
                a2a = ffma2(xlo, wA2[2 * m4],     a2a);
                a2b = ffma2(xhi, wA2[2 * m4 + 1], a2b);
                b2a = ffma2(xlo, wB2[2 * m4],     b2a);
                b2b = ffma2(xhi, wB2[2 * m4 + 1], b2b);
            }
            float u0, u1, u2, u3;
            unpack2(a2a, u0, u1); unpack2(a2b, u2, u3);
            const float va = biasA + ((u0 + u1) + (u2 + u3));
            unpack2(b2a, u0, u1); unpack2(b2b, u2, u3);
            const float vb = biasB + ((u0 + u1) + (u2 + u3));

            float* orow = g_xproj + (size_t)(rbase + r) * PCOLS;
            orow[lane] = va;
            if (lane < 8) orow[32 + lane] = vb;
        }
    }
}

// ---------------------------------------------------------------------------
// Kernel 2: the recurrence. One warp per batch element, lane = g*8 + j.
// Exchanges via smem: h (1 STS + 2 LDS.128, feeds BOTH h-dots),
// {z,cw} packed float2 (1 STS.64 + 4 LDS.128 delivers all 8 z and all 8 cw).
// Gate gather stays 4 SHFL. xproj prefetched 1 step ahead via LDG.
// ---------------------------------------------------------------------------
__global__ void __launch_bounds__(THREADS)
qlstm_rec(const float* __restrict__ Wf, const float* __restrict__ Wi,
          const float* __restrict__ Wu, const float* __restrict__ Wo,
          const float* __restrict__ Wh2k, const float* __restrict__ bh2k,
          float* __restrict__ out)
{
    const int lane = threadIdx.x & 31;
    const int w    = threadIdx.x >> 5;
    const int b    = blockIdx.x * WARPS_PER_BLOCK + w;
    const int g    = lane >> 3;
    const int j    = lane & 7;
    const int base = lane & 24;

    const float* WA = (g == 0) ? Wf : (g == 1) ? Wi : (g == 2) ? Wu : Wo;

    ull wh2[4], whk2[4];
    #pragma unroll
    for (int k2 = 0; k2 < 4; k2++) {
        wh2[k2]  = pack2(WA[(IN_DIM + 2 * k2) * HID + j], WA[(IN_DIM + 2 * k2 + 1) * HID + j]);
        whk2[k2] = pack2(Wh2k[(2 * k2) * HID + j],        Wh2k[(2 * k2 + 1) * HID + j]);
    }
    const float bkx  = bh2k[j];
    const float scl  = (g == 2) ? 2.0f : 1.0f;     // tanh = 2*sigmoid(2a)-1
    const float addc = (g == 2) ? -1.0f : 0.0f;

    __shared__ __align__(16) float zc[WARPS_PER_BLOCK][64];   // {z,cw} per lane
    __shared__ __align__(16) float hb[WARPS_PER_BLOCK][8];    // h state

    if (lane < 8) hb[w][lane] = 0.0f;

    const float* xp0 = g_xproj + (size_t)b * PCOLS;
    const size_t tstride = (size_t)BSZ * PCOLS;

    float px = xp0[lane];          // gate proj (bias+theta included)
    float pk = xp0[32 + j];        // ky (bias included)
    float c = 0.0f, h = 0.0f;
    __syncwarp();

    #pragma unroll 1
    for (int t = 0; t < T_STEPS; t++) {
        const int tn = (t + 1 < T_STEPS) ? (t + 1) : t;
        const float* xpn = xp0 + (size_t)tn * tstride;
        const float npx = __ldg(xpn + lane);
        const float npk = __ldg(xpn + 32 + j);

        // h-dependent dots (h from smem, one load pair feeds both)
        const float4 h4a = *(const float4*)&hb[w][0];
        const float4 h4b = *(const float4*)&hb[w][4];
        const ull h01 = pack2(h4a.x, h4a.y), h23 = pack2(h4a.z, h4a.w);
        const ull h45 = pack2(h4b.x, h4b.y), h67 = pack2(h4b.z, h4b.w);
        ull a2  = ffma2(h01, wh2[0], 0ull);
        ull a2x = ffma2(h23, wh2[1], 0ull);
        a2  = ffma2(h45, wh2[2], a2);
        a2x = ffma2(h67, wh2[3], a2x);
        ull k2  = ffma2(h01, whk2[0], 0ull);
        ull k2x = ffma2(h23, whk2[1], 0ull);
        k2  = ffma2(h45, whk2[2], k2);
        k2x = ffma2(h67, whk2[3], k2x);
        float s0, s1, s2, s3;
        unpack2(a2, s0, s1); unpack2(a2x, s2, s3);
        const float acc = px + ((s0 + s1) + (s2 + s3));
        unpack2(k2, s0, s1); unpack2(k2x, s2, s3);
        const float kx = bkx + ((s0 + s1) + (s2 + s3));

        const float z  = __cosf(acc);
        const float cw = __cosf(0.5f * (kx - pk));

        // exchange z and cw in one shot
        *(float2*)&zc[w][2 * lane] = make_float2(z, cw);
        __syncwarp();
        const float4* zp = (const float4*)&zc[w][2 * base];
        const float4 p0 = zp[0], p1 = zp[1], p2 = zp[2], p3 = zp[3];
        const float zv0 = p0.x, zv1 = p0.z, zv2 = p1.x, zv3 = p1.z;
        const float zv4 = p2.x, zv5 = p2.z, zv6 = p3.x, zv7 = p3.z;

        // qlayer masked prefix product (exact closed form)
        const float m0 = (j == 0) ? 1.0f : zv0;
        const float m2 = (j == 0 || j >= 2) ? zv2 : 1.0f;
        const float m3 = (j == 0 || j >= 3) ? zv3 : 1.0f;
        const float m4 = (j == 0 || j >= 4) ? zv4 : 1.0f;
        const float m5 = (j == 0 || j >= 5) ? zv5 : 1.0f;
        const float m6 = (j == 0 || j >= 6) ? zv6 : 1.0f;
        const float m7 = (j == 7 || j == 0) ? zv7 : 1.0f;
        const float q = ((m0 * zv1) * (m2 * m3)) * ((m4 * m5) * (m6 * m7));

        // quantum kernel weight: |prod of all 8 cw|
        const float wk = fabsf(((p0.y * p0.w) * (p1.y * p1.w)) *
                               ((p2.y * p2.w) * (p3.y * p3.w)));

        const float a = q * wk;

        // branchless sigmoid / tanh
        const float e = __expf(-scl * a);
        const float s = __fdividef(1.0f, 1.0f + e);
        const float gate = s * scl + addc;

        const float fv = __shfl_sync(FULLMASK, gate, j);
        const float iv = __shfl_sync(FULLMASK, gate, 8 + j);
        const float uv = __shfl_sync(FULLMASK, gate, 16 + j);
        const float ov = __shfl_sync(FULLMASK, gate, 24 + j);

        c = fv * c + iv * uv;
        const float e2 = __expf(-2.0f * c);
        const float tc = __fdividef(2.0f, 1.0f + e2) - 1.0f;  // tanh(c)
        h = ov * tc;

        if (lane < 8) {
            out[((size_t)t * BSZ + b) * HID + lane] = h;
            hb[w][lane] = h;                                  // next step's h
        }
        px = npx; pk = npk;
        __syncwarp();
    }

    if (lane < 8) {
        const size_t offh = (size_t)T_STEPS * BSZ * HID;
        out[offh + (size_t)b * HID + lane] = h;                         // hx
        out[offh + (size_t)BSZ * HID + (size_t)b * HID + lane] = c;     // cx
    }
}

extern "C" void kernel_launch(void* const* d_in, const int* in_sizes, int n_in,
                              void* d_out, int out_size)
{
    (void)in_sizes; (void)n_in; (void)out_size;
    // Input order = setup_inputs() dict insertion order:
    // inputs, (Wf,bf,th_f), (Wi,bi,th_i), (Wu,bu,th_u), (Wo,bo,th_o),
    // Wh2k, bh2k, Wi2k, bi2k
    const float* x    = (const float*)d_in[0];
    const float* Wf   = (const float*)d_in[1];
    const float* bf   = (const float*)d_in[2];
    const float* th_f = (const float*)d_in[3];
    const float* Wi   = (const float*)d_in[4];
    const float* bi   = (const float*)d_in[5];
    const float* th_i = (const float*)d_in[6];
    const float* Wu   = (const float*)d_in[7];
    const float* bu   = (const float*)d_in[8];
    const float* th_u = (const float*)d_in[9];
    const float* Wo   = (const float*)d_in[10];
    const float* bo   = (const float*)d_in[11];
    const float* th_o = (const float*)d_in[12];
    const float* Wh2k = (const float*)d_in[13];
    const float* bh2k = (const float*)d_in[14];
    const float* Wi2k = (const float*)d_in[15];
    const float* bi2k = (const float*)d_in[16];

    proj_kernel<<<NROWS / 512, 128>>>(x,
                                      Wf, bf, th_f, Wi, bi, th_i,
                                      Wu, bu, th_u, Wo, bo, th_o,
                                      Wi2k, bi2k);
    qlstm_rec<<<NBLOCKS, THREADS>>>(Wf, Wi, Wu, Wo, Wh2k, bh2k, (float*)d_out);
}

// round 16
// speedup vs baseline: 1.3637x; 1.3637x over previous
#include <cuda_runtime.h>

// QLSTM, two kernels:
//  1) proj_kernel: xproj[t,b,48] = x @ [Wgates_x | Wi2k] + (bias+theta | bi2k)
//  2) qlstm_rec: 512-step recurrence, one warp per batch element, smem
//     exchanges, xproj software-pipelined 4 steps deep (DRAM latency hiding).

#define FULLMASK 0xffffffffu

static constexpr int T_STEPS = 512;
static constexpr int BSZ     = 1024;
static constexpr int IN_DIM  = 64;
static constexpr int HID     = 8;
static constexpr int PCOLS   = 48;            // 32 gate cols + 8 ky cols + 8 pad
static constexpr int WARPS_PER_BLOCK = 4;
static constexpr int THREADS = WARPS_PER_BLOCK * 32;
static constexpr int NBLOCKS = BSZ / WARPS_PER_BLOCK;
static constexpr int NROWS   = T_STEPS * BSZ; // 524288
static constexpr int XS_STR  = 68;            // padded row stride (bank-conflict-free groups)

typedef unsigned long long ull;

__device__ float g_xproj[(size_t)NROWS * PCOLS];   // ~100 MB static scratch

__device__ __forceinline__ ull pack2(float lo, float hi) {
    ull r;
    asm("mov.b64 %0, {%1, %2};" : "=l"(r) : "f"(lo), "f"(hi));
    return r;
}
__device__ __forceinline__ void unpack2(ull v, float& lo, float& hi) {
    asm("mov.b64 {%0, %1}, %2;" : "=f"(lo), "=f"(hi) : "l"(v));
}
__device__ __forceinline__ ull ffma2(ull a, ull b, ull c) {
    ull d;
    asm("fma.rn.f32x2 %0, %1, %2, %3;" : "=l"(d) : "l"(a), "l"(b), "l"(c));
    return d;
}

// ---------------------------------------------------------------------------
// Kernel 1: x projections. Block = 128 threads; 512 rows/block in 4 chunks
// of 128 rows. A-part: lane = gate column (g*8+j), per-row dot, 4 rows
// unrolled. B-part (ky, 8 cols): de-duplicated — each 8-lane group computes
// ky for a DIFFERENT row (4 rows per pass), lane col = lane&7.
// ---------------------------------------------------------------------------
__global__ void __launch_bounds__(128)
proj_kernel(const float* __restrict__ x,
            const float* __restrict__ Wf, const float* __restrict__ bf, const float* __restrict__ th_f,
            const float* __restrict__ Wi, const float* __restrict__ bi, const float* __restrict__ th_i,
            const float* __restrict__ Wu, const float* __restrict__ bu, const float* __restrict__ th_u,
            const float* __restrict__ Wo, const float* __restrict__ bo, const float* __restrict__ th_o,
            const float* __restrict__ Wi2k, const float* __restrict__ bi2k)
{
    __shared__ __align__(16) float xs[128 * XS_STR];
    const int tid  = threadIdx.x;
    const int lane = tid & 31;
    const int w    = tid >> 5;
    const int g    = lane >> 3;
    const int j    = lane & 7;

    const float* WA = (g == 0) ? Wf : (g == 1) ? Wi : (g == 2) ? Wu : Wo;
    const float* bA = (g == 0) ? bf : (g == 1) ? bi : (g == 2) ? bu : bo;
    const float* tA = (g == 0) ? th_f : (g == 1) ? th_i : (g == 2) ? th_u : th_o;

    ull wA2[32], wB2[32];
    #pragma unroll
    for (int m = 0; m < 32; m++) {
        wA2[m] = pack2(WA[(2 * m) * HID + j], WA[(2 * m + 1) * HID + j]);
        wB2[m] = pack2(Wi2k[(2 * m) * HID + j], Wi2k[(2 * m + 1) * HID + j]);
    }
    const float biasA = bA[j] + tA[j];        // bias + RX theta folded
    const float biasB = bi2k[j];

    const int row0 = blockIdx.x * 512;
    for (int chunk = 0; chunk < 4; chunk++) {
        const int rbase = row0 + chunk * 128;
        __syncthreads();                       // protect xs reuse across chunks
        // stage 128 rows x 64 floats into padded layout (stride 68)
        {
            const float4* src = (const float4*)(x + (size_t)rbase * IN_DIM);
            #pragma unroll
            for (int k2 = 0; k2 < 16; k2++) {
                const int e4 = tid + k2 * 128;      // float4 index
                const int r  = e4 >> 4;
                const int c4 = e4 & 15;
                *((float4*)(xs + r * XS_STR) + c4) = src[e4];
            }
        }
        __syncthreads();

        // warp w handles rows [w*32, w*32+32)
        for (int ri = 0; ri < 32; ri += 4) {
            float va[4];
            #pragma unroll
            for (int rr = 0; rr < 4; rr++) {
                const float4* xr = (const float4*)(xs + (w * 32 + ri + rr) * XS_STR);
                ull a2a = 0ull, a2b = 0ull;
                #pragma unroll
                for (int m4 = 0; m4 < 16; m4++) {
                    float4 xv = xr[m4];
                    a2a = ffma2(pack2(xv.x, xv.y), wA2[2 * m4],     a2a);
                    a2b = ffma2(pack2(xv.z, xv.w), wA2[2 * m4 + 1], a2b);
                }
                float u0, u1, u2, u3;
                unpack2(a2a, u0, u1); unpack2(a2b, u2, u3);
                va[rr] = biasA + ((u0 + u1) + (u2 + u3));
            }
            // B-part: each 8-lane group g does row ri+g, column j
            const int rb = w * 32 + ri + g;
            {
                const float4* xr = (const float4*)(xs + rb * XS_STR);
                ull b2a = 0ull, b2b = 0ull;
                #pragma unroll
                for (int m4 = 0; m4 < 16; m4++) {
                    float4 xv = xr[m4];
                    b2a = ffma2(pack2(xv.x, xv.y), wB2[2 * m4],     b2a);
                    b2b = ffma2(pack2(xv.z, xv.w), wB2[2 * m4 + 1], b2b);
                }
                float u0, u1, u2, u3;
                unpack2(b2a, u0, u1); unpack2(b2b, u2, u3);
                const float vb = biasB + ((u0 + u1) + (u2 + u3));
                g_xproj[(size_t)(rbase + rb) * PCOLS + 32 + j] = vb;
            }
            #pragma unroll
            for (int rr = 0; rr < 4; rr++)
                g_xproj[(size_t)(rbase + w * 32 + ri + rr) * PCOLS + lane] = va[rr];
        }
    }
}

// ---------------------------------------------------------------------------
// Kernel 2: the recurrence. One warp per batch element, lane = g*8 + j.
// h via smem (1 STS + 2 LDS.128 feeds both h-dots); {z,cw} via packed float2
// (1 STS.64 + 4 LDS.128). Gate gather = 4 SHFL. xproj prefetched 4 steps
// ahead through rotating register buffers (hides ~600-1000cyc DRAM latency).
// ---------------------------------------------------------------------------
__global__ void __launch_bounds__(THREADS)
qlstm_rec(const float* __restrict__ Wf, const float* __restrict__ Wi,
          const float* __restrict__ Wu, const float* __restrict__ Wo,
          const float* __restrict__ Wh2k, const float* __restrict__ bh2k,
          float* __restrict__ out)
{
    const int lane = threadIdx.x & 31;
    const int w    = threadIdx.x >> 5;
    const int b    = blockIdx.x * WARPS_PER_BLOCK + w;
    const int g    = lane >> 3;
    const int j    = lane & 7;
    const int base = lane & 24;

    const float* WA = (g == 0) ? Wf : (g == 1) ? Wi : (g == 2) ? Wu : Wo;

    ull wh2[4], whk2[4];
    #pragma unroll
    for (int k2 = 0; k2 < 4; k2++) {
        wh2[k2]  = pack2(WA[(IN_DIM + 2 * k2) * HID + j], WA[(IN_DIM + 2 * k2 + 1) * HID + j]);
        whk2[k2] = pack2(Wh2k[(2 * k2) * HID + j],        Wh2k[(2 * k2 + 1) * HID + j]);
    }
    const float bkx  = bh2k[j];
    const float scl  = (g == 2) ? 2.0f : 1.0f;     // tanh = 2*sigmoid(2a)-1
    const float addc = (g == 2) ? -1.0f : 0.0f;

    __shared__ __align__(16) float zc[WARPS_PER_BLOCK][64];   // {z,cw} per lane
    __shared__ __align__(16) float hb[WARPS_PER_BLOCK][8];    // h state

    if (lane < 8) hb[w][lane] = 0.0f;

    const float* xp0 = g_xproj + (size_t)b * PCOLS;
    const size_t tstride = (size_t)BSZ * PCOLS;

    // prefetch pipeline, depth 4
    float pxb[4], pkb[4];
    #pragma unroll
    for (int d = 0; d < 4; d++) {
        pxb[d] = __ldg(xp0 + (size_t)d * tstride + lane);
        pkb[d] = __ldg(xp0 + (size_t)d * tstride + 32 + j);
    }
    float c = 0.0f, h = 0.0f;
    __syncwarp();

    #pragma unroll 1
    for (int t = 0; t < T_STEPS; t += 4) {
        #pragma unroll
        for (int u = 0; u < 4; u++) {
            const int tl = (t + u + 4 < T_STEPS) ? (t + u + 4) : (T_STEPS - 1);
            const float* xpn = xp0 + (size_t)tl * tstride;
            const float npx = __ldg(xpn + lane);
            const float npk = __ldg(xpn + 32 + j);

            const float px = pxb[u];
            const float pk = pkb[u];

            // h-dependent dots (h from smem, one load pair feeds both)
            const float4 h4a = *(const float4*)&hb[w][0];
            const float4 h4b = *(const float4*)&hb[w][4];
            const ull h01 = pack2(h4a.x, h4a.y), h23 = pack2(h4a.z, h4a.w);
            const ull h45 = pack2(h4b.x, h4b.y), h67 = pack2(h4b.z, h4b.w);
            ull a2  = ffma2(h01, wh2[0], 0ull);
            ull a2x = ffma2(h23, wh2[1], 0ull);
            a2  = ffma2(h45, wh2[2], a2);
            a2x = ffma2(h67, wh2[3], a2x);
            ull k2  = ffma2(h01, whk2[0], 0ull);
            ull k2x = ffma2(h23, whk2[1], 0ull);
            k2  = ffma2(h45, whk2[2], k2);
            k2x = ffma2(h67, whk2[3], k2x);
            float s0, s1, s2, s3;
            unpack2(a2, s0, s1); unpack2(a2x, s2, s3);
            const float acc = px + ((s0 + s1) + (s2 + s3));
            unpack2(k2, s0, s1); unpack2(k2x, s2, s3);
            const float kx = bkx + ((s0 + s1) + (s2 + s3));

            const float z  = __cosf(acc);
            const float cw = __cosf(0.5f * (kx - pk));

            // exchange z and cw in one shot
            *(float2*)&zc[w][2 * lane] = make_float2(z, cw);
            __syncwarp();
            const float4* zp = (const float4*)&zc[w][2 * base];
            const float4 p0 = zp[0], p1 = zp[1], p2 = zp[2], p3 = zp[3];
            const float zv0 = p0.x, zv1 = p0.z, zv2 = p1.x, zv3 = p1.z;
            const float zv4 = p2.x, zv5 = p2.z, zv6 = p3.x, zv7 = p3.z;

            // qlayer masked prefix product (exact closed form)
            const float m0 = (j == 0) ? 1.0f : zv0;
            const float m2 = (j == 0 || j >= 2) ? zv2 : 1.0f;
            const float m3 = (j == 0 || j >= 3) ? zv3 : 1.0f;
            const float m4 = (j == 0 || j >= 4) ? zv4 : 1.0f;
            const float m5 = (j == 0 || j >= 5) ? zv5 : 1.0f;
            const float m6 = (j == 0 || j >= 6) ? zv6 : 1.0f;
            const float m7 = (j == 7 || j == 0) ? zv7 : 1.0f;
            const float q = ((m0 * zv1) * (m2 * m3)) * ((m4 * m5) * (m6 * m7));

            // quantum kernel weight: |prod of all 8 cw|
            const float wk = fabsf(((p0.y * p0.w) * (p1.y * p1.w)) *
                                   ((p2.y * p2.w) * (p3.y * p3.w)));

            const float a = q * wk;

            // branchless sigmoid / tanh
            const float e = __expf(-scl * a);
            const float s = __fdividef(1.0f, 1.0f + e);
            const float gate = s * scl + addc;

            const float fv = __shfl_sync(FULLMASK, gate, j);
            const float iv = __shfl_sync(FULLMASK, gate, 8 + j);
            const float uv = __shfl_sync(FULLMASK, gate, 16 + j);
            const float ov = __shfl_sync(FULLMASK, gate, 24 + j);

            c = fv * c + iv * uv;
            const float e2 = __expf(-2.0f * c);
            const float tc = __fdividef(2.0f, 1.0f + e2) - 1.0f;  // tanh(c)
            h = ov * tc;

            if (lane < 8) {
                out[((size_t)(t + u) * BSZ + b) * HID + lane] = h;
                hb[w][lane] = h;                                  // next step's h
            }
            pxb[u] = npx; pkb[u] = npk;
            __syncwarp();
        }
    }

    if (lane < 8) {
        const size_t offh = (size_t)T_STEPS * BSZ * HID;
        out[offh + (size_t)b * HID + lane] = h;                         // hx
        out[offh + (size_t)BSZ * HID + (size_t)b * HID + lane] = c;     // cx
    }
}

extern "C" void kernel_launch(void* const* d_in, const int* in_sizes, int n_in,
                              void* d_out, int out_size)
{
    (void)in_sizes; (void)n_in; (void)out_size;
    // Input order = setup_inputs() dict insertion order:
    // inputs, (Wf,bf,th_f), (Wi,bi,th_i), (Wu,bu,th_u), (Wo,bo,th_o),
    // Wh2k, bh2k, Wi2k, bi2k
    const float* x    = (const float*)d_in[0];
    const float* Wf   = (const float*)d_in[1];
    const float* bf   = (const float*)d_in[2];
    const float* th_f = (const float*)d_in[3];
    const float* Wi   = (const float*)d_in[4];
    const float* bi   = (const float*)d_in[5];
    const float* th_i = (const float*)d_in[6];
    const float* Wu   = (const float*)d_in[7];
    const float* bu   = (const float*)d_in[8];
    const float* th_u = (const float*)d_in[9];
    const float* Wo   = (const float*)d_in[10];
    const float* bo   = (const float*)d_in[11];
    const float* th_o = (const float*)d_in[12];
    const float* Wh2k = (const float*)d_in[13];
    const float* bh2k = (const float*)d_in[14];
    const float* Wi2k = (const float*)d_in[15];
    const float* bi2k = (const float*)d_in[16];

    proj_kernel<<<NROWS / 512, 128>>>(x,
                                      Wf, bf, th_f, Wi, bi, th_i,
                                      Wu, bu, th_u, Wo, bo, th_o,
                                      Wi2k, bi2k);
    qlstm_rec<<<NBLOCKS, THREADS>>>(Wf, Wi, Wu, Wo, Wh2k, bh2k, (float*)d_out);
}